// round 1
// baseline (speedup 1.0000x reference)
#include <cuda_runtime.h>
#include <cstddef>

#define DIM     4096
#define SEQ     2048
#define HEADS   32
#define KVHEADS 8
#define HDIM    128
#define KVDIM   1024   // KVHEADS*HDIM

// ------------------------- scratch (static, no allocation) -------------------
__device__ float g_xq[SEQ * DIM];      // 33.5 MB
__device__ float g_xk[SEQ * KVDIM];    //  8.4 MB
__device__ float g_xv[SEQ * KVDIM];    //  8.4 MB
__device__ float g_attn[SEQ * DIM];    // 33.5 MB

// ============================================================================
// GEMM: C[M,N] = A[M,K] * B[N,K]^T   (both row-major, K contiguous)
// 128x128 tile, BK=16, 256 threads, 8x8 per-thread micro-tile (2 x 4x4 split)
// If blockIdx.z == 1, uses (B2, C2) instead — lets K and V projections share
// one launch for better SM occupancy.
// ============================================================================
#define GBM 128
#define GBN 128
#define GBK 16
#define GPAD 132

__global__ void __launch_bounds__(256, 2) gemm_nt_kernel(
    const float* __restrict__ A, const float* __restrict__ B, float* __restrict__ C,
    const float* __restrict__ B2, float* __restrict__ C2,
    int M, int N, int K)
{
    if (blockIdx.z == 1) { B = B2; C = C2; }

    __shared__ float As[GBK * GPAD];
    __shared__ float Bs[GBK * GPAD];

    const int tid = threadIdx.x;
    const int tx = tid & 15;
    const int ty = tid >> 4;
    const int bm = blockIdx.y * GBM;
    const int bn = blockIdx.x * GBN;

    // loader mapping: each thread fetches one float4 from row lm and row lm+64
    const int lm = tid >> 2;          // 0..63
    const int lk = (tid & 3) << 2;    // 0,4,8,12

    const float* Ap = A + (size_t)(bm + lm) * K + lk;
    const float* Bp = B + (size_t)(bn + lm) * K + lk;

    float acc[8][8];
    #pragma unroll
    for (int i = 0; i < 8; i++)
        #pragma unroll
        for (int j = 0; j < 8; j++) acc[i][j] = 0.0f;

    // prefetch first tile
    float4 a0 = *(const float4*)(Ap);
    float4 a1 = *(const float4*)(Ap + (size_t)64 * K);
    float4 b0 = *(const float4*)(Bp);
    float4 b1 = *(const float4*)(Bp + (size_t)64 * K);

    for (int k0 = 0; k0 < K; k0 += GBK) {
        __syncthreads();
        As[(lk + 0) * GPAD + lm]      = a0.x;
        As[(lk + 1) * GPAD + lm]      = a0.y;
        As[(lk + 2) * GPAD + lm]      = a0.z;
        As[(lk + 3) * GPAD + lm]      = a0.w;
        As[(lk + 0) * GPAD + lm + 64] = a1.x;
        As[(lk + 1) * GPAD + lm + 64] = a1.y;
        As[(lk + 2) * GPAD + lm + 64] = a1.z;
        As[(lk + 3) * GPAD + lm + 64] = a1.w;
        Bs[(lk + 0) * GPAD + lm]      = b0.x;
        Bs[(lk + 1) * GPAD + lm]      = b0.y;
        Bs[(lk + 2) * GPAD + lm]      = b0.z;
        Bs[(lk + 3) * GPAD + lm]      = b0.w;
        Bs[(lk + 0) * GPAD + lm + 64] = b1.x;
        Bs[(lk + 1) * GPAD + lm + 64] = b1.y;
        Bs[(lk + 2) * GPAD + lm + 64] = b1.z;
        Bs[(lk + 3) * GPAD + lm + 64] = b1.w;
        __syncthreads();

        // prefetch next tile while computing this one
        if (k0 + GBK < K) {
            const int koff = k0 + GBK;
            a0 = *(const float4*)(Ap + koff);
            a1 = *(const float4*)(Ap + (size_t)64 * K + koff);
            b0 = *(const float4*)(Bp + koff);
            b1 = *(const float4*)(Bp + (size_t)64 * K + koff);
        }

        #pragma unroll
        for (int k = 0; k < GBK; k++) {
            float ar[8], br[8];
            *(float4*)&ar[0] = *(const float4*)&As[k * GPAD + 4 * ty];
            *(float4*)&ar[4] = *(const float4*)&As[k * GPAD + 64 + 4 * ty];
            *(float4*)&br[0] = *(const float4*)&Bs[k * GPAD + 4 * tx];
            *(float4*)&br[4] = *(const float4*)&Bs[k * GPAD + 64 + 4 * tx];
            #pragma unroll
            for (int i = 0; i < 8; i++)
                #pragma unroll
                for (int j = 0; j < 8; j++)
                    acc[i][j] += ar[i] * br[j];
        }
    }

    #pragma unroll
    for (int i = 0; i < 8; i++) {
        const int r = bm + ((i < 4) ? (4 * ty + i) : (64 + 4 * ty + (i - 4)));
        float4 o0 = make_float4(acc[i][0], acc[i][1], acc[i][2], acc[i][3]);
        float4 o1 = make_float4(acc[i][4], acc[i][5], acc[i][6], acc[i][7]);
        *(float4*)&C[(size_t)r * N + bn + 4 * tx]      = o0;
        *(float4*)&C[(size_t)r * N + bn + 64 + 4 * tx] = o1;
    }
}

// ============================================================================
// RoPE (interleaved pairs), in place. t layout: [SEQ][nheads][HDIM]
// ============================================================================
__global__ void rope_kernel(float* __restrict__ t,
                            const float* __restrict__ fc,
                            const float* __restrict__ fs,
                            int nheads)
{
    const int idx = blockIdx.x * blockDim.x + threadIdx.x;
    const int total = SEQ * nheads * (HDIM / 2);
    if (idx >= total) return;
    const int p  = idx & 63;          // pair index 0..63
    const int t2 = idx >> 6;
    const int hh = t2 % nheads;
    const int s  = t2 / nheads;
    const float c  = fc[s * 64 + p];
    const float sn = fs[s * 64 + p];
    const size_t base = ((size_t)s * nheads + hh) * HDIM + 2 * p;
    const float a = t[base];
    const float b = t[base + 1];
    t[base]     = a * c - b * sn;
    t[base + 1] = a * sn + b * c;
}

// ============================================================================
// Flash attention, fp32, causal, GQA (4 Q heads per KV head).
// One CTA = (head h, 64-row q tile). 256 threads as 16x16, 4x4 S micro-tile,
// 4x8 O micro-tile. Full head-dim (128) of Q^T and K^T staged in smem.
// ============================================================================
#define FPAD 65
#define PPAD 66
#define FLASH_SMEM ((128 * FPAD * 2 + 64 * HDIM + 64 * PPAD) * 4)

__global__ void __launch_bounds__(256) flash_kernel(
    const float* __restrict__ Qg, const float* __restrict__ Kg,
    const float* __restrict__ Vg, float* __restrict__ Og)
{
    extern __shared__ float sm[];
    float* Qt = sm;                     // [128][FPAD]  Q^T
    float* Kt = Qt + 128 * FPAD;        // [128][FPAD]  K^T
    float* Vs = Kt + 128 * FPAD;        // [64][128]
    float* Ps = Vs + 64 * HDIM;         // [64][PPAD]

    const int qt   = gridDim.x - 1 - blockIdx.x;   // heavy tiles first
    const int h    = blockIdx.y;
    const int kvh  = h >> 2;
    const int qbase = qt * 64;
    const int tid = threadIdx.x;
    const int tx = tid & 15;
    const int ty = tid >> 4;

    // load Q tile transposed
    #pragma unroll
    for (int f = tid; f < 2048; f += 256) {
        const int m = f >> 5;
        const int d = (f & 31) << 2;
        float4 v = *(const float4*)(Qg + (size_t)(qbase + m) * DIM + h * HDIM + d);
        Qt[(d + 0) * FPAD + m] = v.x;
        Qt[(d + 1) * FPAD + m] = v.y;
        Qt[(d + 2) * FPAD + m] = v.z;
        Qt[(d + 3) * FPAD + m] = v.w;
    }

    float m_i[4], l_i[4], o_acc[4][8];
    #pragma unroll
    for (int i = 0; i < 4; i++) {
        m_i[i] = -1e30f;
        l_i[i] = 0.0f;
        #pragma unroll
        for (int j = 0; j < 8; j++) o_acc[i][j] = 0.0f;
    }
    const float scale = 0.08838834764831843f;  // 1/sqrt(128)

    for (int kt = 0; kt <= qt; kt++) {
        const int kbase = kt * 64;
        __syncthreads();   // prior iter done reading Kt/Vs/Ps (also orders Qt on iter 0)

        // load K^T and V tiles
        #pragma unroll
        for (int f = tid; f < 2048; f += 256) {
            const int n = f >> 5;
            const int d = (f & 31) << 2;
            const size_t gi = (size_t)(kbase + n) * KVDIM + kvh * HDIM + d;
            float4 kv = *(const float4*)(Kg + gi);
            Kt[(d + 0) * FPAD + n] = kv.x;
            Kt[(d + 1) * FPAD + n] = kv.y;
            Kt[(d + 2) * FPAD + n] = kv.z;
            Kt[(d + 3) * FPAD + n] = kv.w;
            *(float4*)&Vs[n * HDIM + d] = *(const float4*)(Vg + gi);
        }
        __syncthreads();

        // S = Q K^T (4x4 per thread)
        float s[4][4];
        #pragma unroll
        for (int i = 0; i < 4; i++)
            #pragma unroll
            for (int j = 0; j < 4; j++) s[i][j] = 0.0f;

        #pragma unroll 8
        for (int k = 0; k < HDIM; k++) {
            float a[4], b[4];
            #pragma unroll
            for (int i = 0; i < 4; i++) a[i] = Qt[k * FPAD + 4 * ty + i];
            #pragma unroll
            for (int j = 0; j < 4; j++) b[j] = Kt[k * FPAD + 4 * tx + j];
            #pragma unroll
            for (int i = 0; i < 4; i++)
                #pragma unroll
                for (int j = 0; j < 4; j++)
                    s[i][j] += a[i] * b[j];
        }

        const bool diag = (kt == qt);
        #pragma unroll
        for (int i = 0; i < 4; i++) {
            const int rg = qbase + 4 * ty + i;
            #pragma unroll
            for (int j = 0; j < 4; j++) {
                float sv = s[i][j] * scale;
                if (diag && (kbase + 4 * tx + j > rg)) sv = -1e30f;
                s[i][j] = sv;
            }
        }

        // online softmax: row reduce across the 16-lane tx group
        #pragma unroll
        for (int i = 0; i < 4; i++) {
            float rmax = fmaxf(fmaxf(s[i][0], s[i][1]), fmaxf(s[i][2], s[i][3]));
            rmax = fmaxf(rmax, __shfl_xor_sync(0xffffffffu, rmax, 8));
            rmax = fmaxf(rmax, __shfl_xor_sync(0xffffffffu, rmax, 4));
            rmax = fmaxf(rmax, __shfl_xor_sync(0xffffffffu, rmax, 2));
            rmax = fmaxf(rmax, __shfl_xor_sync(0xffffffffu, rmax, 1));
            const float mnew = fmaxf(m_i[i], rmax);
            const float corr = __expf(m_i[i] - mnew);
            float rs = 0.0f;
            #pragma unroll
            for (int j = 0; j < 4; j++) {
                const float p = __expf(s[i][j] - mnew);
                s[i][j] = p;
                rs += p;
            }
            rs += __shfl_xor_sync(0xffffffffu, rs, 8);
            rs += __shfl_xor_sync(0xffffffffu, rs, 4);
            rs += __shfl_xor_sync(0xffffffffu, rs, 2);
            rs += __shfl_xor_sync(0xffffffffu, rs, 1);
            l_i[i] = l_i[i] * corr + rs;
            m_i[i] = mnew;
            #pragma unroll
            for (int jj = 0; jj < 8; jj++) o_acc[i][jj] *= corr;
            #pragma unroll
            for (int j = 0; j < 4; j++)
                Ps[(4 * ty + i) * PPAD + 4 * tx + j] = s[i][j];
        }
        __syncthreads();

        // O += P V   (4 rows x 8 dim-cols per thread)
        #pragma unroll 8
        for (int n = 0; n < 64; n++) {
            float4 v0 = *(const float4*)&Vs[n * HDIM + 8 * tx];
            float4 v1 = *(const float4*)&Vs[n * HDIM + 8 * tx + 4];
            #pragma unroll
            for (int i = 0; i < 4; i++) {
                const float p = Ps[(4 * ty + i) * PPAD + n];
                o_acc[i][0] += p * v0.x;
                o_acc[i][1] += p * v0.y;
                o_acc[i][2] += p * v0.z;
                o_acc[i][3] += p * v0.w;
                o_acc[i][4] += p * v1.x;
                o_acc[i][5] += p * v1.y;
                o_acc[i][6] += p * v1.z;
                o_acc[i][7] += p * v1.w;
            }
        }
    }

    // epilogue: normalize and write [SEQ][HEADS*HDIM]
    #pragma unroll
    for (int i = 0; i < 4; i++) {
        const float inv = 1.0f / l_i[i];
        const int r = qbase + 4 * ty + i;
        float4 o0 = make_float4(o_acc[i][0] * inv, o_acc[i][1] * inv,
                                o_acc[i][2] * inv, o_acc[i][3] * inv);
        float4 o1 = make_float4(o_acc[i][4] * inv, o_acc[i][5] * inv,
                                o_acc[i][6] * inv, o_acc[i][7] * inv);
        *(float4*)&Og[(size_t)r * DIM + h * HDIM + 8 * tx]     = o0;
        *(float4*)&Og[(size_t)r * DIM + h * HDIM + 8 * tx + 4] = o1;
    }
}

// ============================================================================
// launch
// ============================================================================
extern "C" void kernel_launch(void* const* d_in, const int* in_sizes, int n_in,
                              void* d_out, int out_size)
{
    (void)in_sizes; (void)n_in; (void)out_size;
    const float* x  = (const float*)d_in[0];
    const float* wq = (const float*)d_in[1];
    const float* wk = (const float*)d_in[2];
    const float* wv = (const float*)d_in[3];
    const float* wo = (const float*)d_in[4];
    const float* fc = (const float*)d_in[5];
    const float* fs = (const float*)d_in[6];
    float* out = (float*)d_out;

    float *xq = nullptr, *xk = nullptr, *xv = nullptr, *attn = nullptr;
    cudaGetSymbolAddress((void**)&xq,   g_xq);
    cudaGetSymbolAddress((void**)&xk,   g_xk);
    cudaGetSymbolAddress((void**)&xv,   g_xv);
    cudaGetSymbolAddress((void**)&attn, g_attn);

    // 1) Q projection: [2048,4096] = x @ wq^T
    gemm_nt_kernel<<<dim3(DIM / GBN, SEQ / GBM, 1), 256>>>(
        x, wq, xq, nullptr, nullptr, SEQ, DIM, DIM);

    // 2) K and V projections in one launch (z = 0 -> K, z = 1 -> V)
    gemm_nt_kernel<<<dim3(KVDIM / GBN, SEQ / GBM, 2), 256>>>(
        x, wk, xk, wv, xv, SEQ, KVDIM, DIM);

    // 3) RoPE on Q and K
    {
        const int nq = SEQ * HEADS * (HDIM / 2);
        rope_kernel<<<(nq + 255) / 256, 256>>>(xq, fc, fs, HEADS);
        const int nk = SEQ * KVHEADS * (HDIM / 2);
        rope_kernel<<<(nk + 255) / 256, 256>>>(xk, fc, fs, KVHEADS);
    }

    // 4) causal flash attention
    cudaFuncSetAttribute(flash_kernel,
                         cudaFuncAttributeMaxDynamicSharedMemorySize, FLASH_SMEM);
    flash_kernel<<<dim3(SEQ / 64, HEADS), 256, FLASH_SMEM>>>(xq, xk, xv, attn);

    // 5) output projection: out = attn @ wo^T
    gemm_nt_kernel<<<dim3(DIM / GBN, SEQ / GBM, 1), 256>>>(
        attn, wo, out, nullptr, nullptr, SEQ, DIM, DIM);
}

// round 2
// speedup vs baseline: 1.5747x; 1.5747x over previous
#include <cuda_runtime.h>
#include <cuda_bf16.h>
#include <cstdint>
#include <cstddef>

#define DIM     4096
#define SEQ     2048
#define HEADS   32
#define KVHEADS 8
#define HDIM    128
#define KVDIM   1024   // KVHEADS*HDIM

// ------------------------- scratch (static, no allocation) -------------------
__device__ float g_xq[SEQ * DIM];      // fp32 Q proj (RoPE'd in place)
__device__ float g_xk[SEQ * KVDIM];
__device__ float g_xv[SEQ * KVDIM];
__device__ float g_attn[SEQ * DIM];

// bf16 hi/lo splits
__device__ __nv_bfloat16 g_xh[SEQ * DIM],    g_xl[SEQ * DIM];
__device__ __nv_bfloat16 g_wqh[DIM * DIM],   g_wql[DIM * DIM];
__device__ __nv_bfloat16 g_wkh[KVDIM * DIM], g_wkl[KVDIM * DIM];
__device__ __nv_bfloat16 g_wvh[KVDIM * DIM], g_wvl[KVDIM * DIM];
__device__ __nv_bfloat16 g_woh[DIM * DIM],   g_wol[DIM * DIM];
__device__ __nv_bfloat16 g_ath[SEQ * DIM],   g_atl[SEQ * DIM];

// ============================================================================
// split: fp32 -> bf16 hi + bf16 lo (lo = bf16(x - float(hi)))
// ============================================================================
__global__ void split_kernel(const float* __restrict__ x,
                             __nv_bfloat16* __restrict__ hi,
                             __nv_bfloat16* __restrict__ lo, int n4)
{
    const int i = blockIdx.x * blockDim.x + threadIdx.x;
    if (i >= n4) return;
    float4 v = ((const float4*)x)[i];
    __nv_bfloat16 h0 = __float2bfloat16(v.x);
    __nv_bfloat16 h1 = __float2bfloat16(v.y);
    __nv_bfloat16 h2 = __float2bfloat16(v.z);
    __nv_bfloat16 h3 = __float2bfloat16(v.w);
    __nv_bfloat16 l0 = __float2bfloat16(v.x - __bfloat162float(h0));
    __nv_bfloat16 l1 = __float2bfloat16(v.y - __bfloat162float(h1));
    __nv_bfloat16 l2 = __float2bfloat16(v.z - __bfloat162float(h2));
    __nv_bfloat16 l3 = __float2bfloat16(v.w - __bfloat162float(h3));
    __nv_bfloat162 hp0 = __halves2bfloat162(h0, h1);
    __nv_bfloat162 hp1 = __halves2bfloat162(h2, h3);
    __nv_bfloat162 lp0 = __halves2bfloat162(l0, l1);
    __nv_bfloat162 lp1 = __halves2bfloat162(l2, l3);
    uint2 hv, lv;
    hv.x = *(uint32_t*)&hp0; hv.y = *(uint32_t*)&hp1;
    lv.x = *(uint32_t*)&lp0; lv.y = *(uint32_t*)&lp1;
    ((uint2*)hi)[i] = hv;
    ((uint2*)lo)[i] = lv;
}

// ============================================================================
// bf16x3 tensor-core GEMM:  C[M,N](fp32) = A[M,K] * B[N,K]^T
// A,B given as bf16 hi/lo pairs. 128x128x32 CTA tile, 256 thr, 8 warps (2x4),
// warp tile 64x32, mma.m16n8k16, cp.async double-buffered smem.
// z==1 switches to (B2,C2) — fuses K and V projections.
// ============================================================================
#define GBK 32                    // bf16 k per tile
#define SMAT 8192                 // one 128x32 bf16 matrix in smem (64B rows)
#define SBUF (4 * SMAT)           // Ah, Al, Bh, Bl
#define GEMM_SMEM (2 * SBUF)      // double buffer = 64KB

// smem byte offset with XOR swizzle (row stride 64B, 16B chunks)
__device__ __forceinline__ uint32_t soff(int row, int chunk) {
    return (uint32_t)((row << 6) + ((chunk ^ ((row >> 1) & 3)) << 4));
}

__device__ __forceinline__ void ldsm4(uint32_t* r, uint32_t addr) {
    asm volatile("ldmatrix.sync.aligned.m8n8.x4.shared.b16 {%0,%1,%2,%3}, [%4];"
                 : "=r"(r[0]), "=r"(r[1]), "=r"(r[2]), "=r"(r[3]) : "r"(addr));
}

__device__ __forceinline__ void mma16816(float* c, const uint32_t* a, const uint32_t* b) {
    asm volatile("mma.sync.aligned.m16n8k16.row.col.f32.bf16.bf16.f32 "
                 "{%0,%1,%2,%3},{%4,%5,%6,%7},{%8,%9},{%0,%1,%2,%3};"
                 : "+f"(c[0]), "+f"(c[1]), "+f"(c[2]), "+f"(c[3])
                 : "r"(a[0]), "r"(a[1]), "r"(a[2]), "r"(a[3]), "r"(b[0]), "r"(b[1]));
}

#define CP16(dst, src) asm volatile("cp.async.cg.shared.global [%0], [%1], 16;" :: "r"(dst), "l"(src))
#define CP_COMMIT()    asm volatile("cp.async.commit_group;")
#define CP_WAIT(n)     asm volatile("cp.async.wait_group %0;" :: "n"(n))

__global__ void __launch_bounds__(256, 2) gemm_bf16x3_kernel(
    const __nv_bfloat16* __restrict__ Ah, const __nv_bfloat16* __restrict__ Al,
    const __nv_bfloat16* Bh, const __nv_bfloat16* Bl, float* C,
    const __nv_bfloat16* B2h, const __nv_bfloat16* B2l, float* C2,
    int M, int N, int K)
{
    if (blockIdx.z == 1) { Bh = B2h; Bl = B2l; C = C2; }

    extern __shared__ char smem[];
    const int tid  = threadIdx.x;
    const int lane = tid & 31;
    const int w    = tid >> 5;
    const int wm   = w >> 2;        // 0..1
    const int wn   = w & 3;         // 0..3
    const int bm   = blockIdx.y * 128;
    const int bn   = blockIdx.x * 128;

    // loader mapping: row = tid>>2 (0..63, +64), chunk = tid&3
    const int lrow = tid >> 2;
    const int lc   = tid & 3;

    const __nv_bfloat16* gA[2] = { Ah, Al };
    const __nv_bfloat16* gB[2] = { Bh, Bl };

    float acc[4][4][4];
    #pragma unroll
    for (int i = 0; i < 4; i++)
        #pragma unroll
        for (int j = 0; j < 4; j++)
            #pragma unroll
            for (int r = 0; r < 4; r++) acc[i][j][r] = 0.0f;

    const uint32_t sbase = (uint32_t)__cvta_generic_to_shared(smem);

    // issue cp.async for tile starting at k0 into buffer b
    auto load_tile = [&](int k0, int b) {
        const uint32_t bufo = sbase + b * SBUF;
        #pragma unroll
        for (int m = 0; m < 2; m++) {   // 0: hi, 1: lo of A
            const __nv_bfloat16* g = gA[m] + (size_t)(bm + lrow) * K + k0 + lc * 8;
            CP16(bufo + m * SMAT + soff(lrow, lc), g);
            CP16(bufo + m * SMAT + soff(lrow + 64, lc), g + (size_t)64 * K);
        }
        #pragma unroll
        for (int m = 0; m < 2; m++) {
            const __nv_bfloat16* g = gB[m] + (size_t)(bn + lrow) * K + k0 + lc * 8;
            CP16(bufo + (2 + m) * SMAT + soff(lrow, lc), g);
            CP16(bufo + (2 + m) * SMAT + soff(lrow + 64, lc), g + (size_t)64 * K);
        }
    };

    const int nIt = K / GBK;
    load_tile(0, 0);
    CP_COMMIT();

    const int rl = lane & 15;        // ldmatrix row within 16
    const int rh = lane >> 4;        // ldmatrix k-half select

    for (int it = 0; it < nIt; ++it) {
        if (it + 1 < nIt) {
            load_tile((it + 1) * GBK, (it + 1) & 1);
            CP_COMMIT();
            CP_WAIT(1);
        } else {
            CP_WAIT(0);
        }
        __syncthreads();

        const uint32_t bufo = sbase + (it & 1) * SBUF;
        const uint32_t sAh = bufo;
        const uint32_t sAl = bufo + SMAT;
        const uint32_t sBh = bufo + 2 * SMAT;
        const uint32_t sBl = bufo + 3 * SMAT;

        #pragma unroll
        for (int ks = 0; ks < 2; ks++) {
            const int chunk = 2 * ks + rh;
            uint32_t ah[4][4], al[4][4], bh[4][2], bl[4][2];

            // A_hi fragments (4 x m16)
            #pragma unroll
            for (int mi = 0; mi < 4; mi++) {
                const int row = wm * 64 + mi * 16 + rl;
                ldsm4(ah[mi], sAh + soff(row, chunk));
            }
            // B_hi fragments (2 x ldmatrix.x4 -> 4 n-frags)
            #pragma unroll
            for (int nb = 0; nb < 2; nb++) {
                uint32_t r4[4];
                const int row = wn * 32 + nb * 16 + rl;
                ldsm4(r4, sBh + soff(row, chunk));
                bh[2 * nb][0] = r4[0]; bh[2 * nb + 1][0] = r4[1];
                bh[2 * nb][1] = r4[2]; bh[2 * nb + 1][1] = r4[3];
            }
            // pass 0: hi * hi
            #pragma unroll
            for (int mi = 0; mi < 4; mi++)
                #pragma unroll
                for (int nj = 0; nj < 4; nj++)
                    mma16816(acc[mi][nj], ah[mi], bh[nj]);

            // B_lo fragments
            #pragma unroll
            for (int nb = 0; nb < 2; nb++) {
                uint32_t r4[4];
                const int row = wn * 32 + nb * 16 + rl;
                ldsm4(r4, sBl + soff(row, chunk));
                bl[2 * nb][0] = r4[0]; bl[2 * nb + 1][0] = r4[1];
                bl[2 * nb][1] = r4[2]; bl[2 * nb + 1][1] = r4[3];
            }
            // pass 1: hi * lo
            #pragma unroll
            for (int mi = 0; mi < 4; mi++)
                #pragma unroll
                for (int nj = 0; nj < 4; nj++)
                    mma16816(acc[mi][nj], ah[mi], bl[nj]);

            // A_lo fragments
            #pragma unroll
            for (int mi = 0; mi < 4; mi++) {
                const int row = wm * 64 + mi * 16 + rl;
                ldsm4(al[mi], sAl + soff(row, chunk));
            }
            // pass 2: lo * hi
            #pragma unroll
            for (int mi = 0; mi < 4; mi++)
                #pragma unroll
                for (int nj = 0; nj < 4; nj++)
                    mma16816(acc[mi][nj], al[mi], bh[nj]);
        }
        __syncthreads();
    }

    // epilogue
    const int tg = lane >> 2;        // 0..7
    const int ti = lane & 3;         // 0..3
    #pragma unroll
    for (int mi = 0; mi < 4; mi++) {
        const int row = bm + wm * 64 + mi * 16 + tg;
        #pragma unroll
        for (int nj = 0; nj < 4; nj++) {
            const int col = bn + wn * 32 + nj * 8 + 2 * ti;
            float2 v0 = make_float2(acc[mi][nj][0], acc[mi][nj][1]);
            float2 v1 = make_float2(acc[mi][nj][2], acc[mi][nj][3]);
            *(float2*)&C[(size_t)row * N + col]       = v0;
            *(float2*)&C[(size_t)(row + 8) * N + col] = v1;
        }
    }
}

// ============================================================================
// RoPE (interleaved pairs), in place. t layout: [SEQ][nheads][HDIM]
// ============================================================================
__global__ void rope_kernel(float* __restrict__ t,
                            const float* __restrict__ fc,
                            const float* __restrict__ fs,
                            int nheads)
{
    const int idx = blockIdx.x * blockDim.x + threadIdx.x;
    const int total = SEQ * nheads * (HDIM / 2);
    if (idx >= total) return;
    const int p  = idx & 63;
    const int t2 = idx >> 6;
    const int hh = t2 % nheads;
    const int s  = t2 / nheads;
    const float c  = fc[s * 64 + p];
    const float sn = fs[s * 64 + p];
    const size_t base = ((size_t)s * nheads + hh) * HDIM + 2 * p;
    const float a = t[base];
    const float b = t[base + 1];
    t[base]     = a * c - b * sn;
    t[base + 1] = a * sn + b * c;
}

// ============================================================================
// Flash attention, fp32, causal, GQA — unchanged from R1.
// ============================================================================
#define FPAD 65
#define PPAD 66
#define FLASH_SMEM ((128 * FPAD * 2 + 64 * HDIM + 64 * PPAD) * 4)

__global__ void __launch_bounds__(256) flash_kernel(
    const float* __restrict__ Qg, const float* __restrict__ Kg,
    const float* __restrict__ Vg, float* __restrict__ Og)
{
    extern __shared__ float sm[];
    float* Qt = sm;
    float* Kt = Qt + 128 * FPAD;
    float* Vs = Kt + 128 * FPAD;
    float* Ps = Vs + 64 * HDIM;

    const int qt   = gridDim.x - 1 - blockIdx.x;
    const int h    = blockIdx.y;
    const int kvh  = h >> 2;
    const int qbase = qt * 64;
    const int tid = threadIdx.x;
    const int tx = tid & 15;
    const int ty = tid >> 4;

    #pragma unroll
    for (int f = tid; f < 2048; f += 256) {
        const int m = f >> 5;
        const int d = (f & 31) << 2;
        float4 v = *(const float4*)(Qg + (size_t)(qbase + m) * DIM + h * HDIM + d);
        Qt[(d + 0) * FPAD + m] = v.x;
        Qt[(d + 1) * FPAD + m] = v.y;
        Qt[(d + 2) * FPAD + m] = v.z;
        Qt[(d + 3) * FPAD + m] = v.w;
    }

    float m_i[4], l_i[4], o_acc[4][8];
    #pragma unroll
    for (int i = 0; i < 4; i++) {
        m_i[i] = -1e30f;
        l_i[i] = 0.0f;
        #pragma unroll
        for (int j = 0; j < 8; j++) o_acc[i][j] = 0.0f;
    }
    const float scale = 0.08838834764831843f;

    for (int kt = 0; kt <= qt; kt++) {
        const int kbase = kt * 64;
        __syncthreads();

        #pragma unroll
        for (int f = tid; f < 2048; f += 256) {
            const int n = f >> 5;
            const int d = (f & 31) << 2;
            const size_t gi = (size_t)(kbase + n) * KVDIM + kvh * HDIM + d;
            float4 kv = *(const float4*)(Kg + gi);
            Kt[(d + 0) * FPAD + n] = kv.x;
            Kt[(d + 1) * FPAD + n] = kv.y;
            Kt[(d + 2) * FPAD + n] = kv.z;
            Kt[(d + 3) * FPAD + n] = kv.w;
            *(float4*)&Vs[n * HDIM + d] = *(const float4*)(Vg + gi);
        }
        __syncthreads();

        float s[4][4];
        #pragma unroll
        for (int i = 0; i < 4; i++)
            #pragma unroll
            for (int j = 0; j < 4; j++) s[i][j] = 0.0f;

        #pragma unroll 8
        for (int k = 0; k < HDIM; k++) {
            float a[4], b[4];
            #pragma unroll
            for (int i = 0; i < 4; i++) a[i] = Qt[k * FPAD + 4 * ty + i];
            #pragma unroll
            for (int j = 0; j < 4; j++) b[j] = Kt[k * FPAD + 4 * tx + j];
            #pragma unroll
            for (int i = 0; i < 4; i++)
                #pragma unroll
                for (int j = 0; j < 4; j++)
                    s[i][j] += a[i] * b[j];
        }

        const bool diag = (kt == qt);
        #pragma unroll
        for (int i = 0; i < 4; i++) {
            const int rg = qbase + 4 * ty + i;
            #pragma unroll
            for (int j = 0; j < 4; j++) {
                float sv = s[i][j] * scale;
                if (diag && (kbase + 4 * tx + j > rg)) sv = -1e30f;
                s[i][j] = sv;
            }
        }

        #pragma unroll
        for (int i = 0; i < 4; i++) {
            float rmax = fmaxf(fmaxf(s[i][0], s[i][1]), fmaxf(s[i][2], s[i][3]));
            rmax = fmaxf(rmax, __shfl_xor_sync(0xffffffffu, rmax, 8));
            rmax = fmaxf(rmax, __shfl_xor_sync(0xffffffffu, rmax, 4));
            rmax = fmaxf(rmax, __shfl_xor_sync(0xffffffffu, rmax, 2));
            rmax = fmaxf(rmax, __shfl_xor_sync(0xffffffffu, rmax, 1));
            const float mnew = fmaxf(m_i[i], rmax);
            const float corr = __expf(m_i[i] - mnew);
            float rs = 0.0f;
            #pragma unroll
            for (int j = 0; j < 4; j++) {
                const float p = __expf(s[i][j] - mnew);
                s[i][j] = p;
                rs += p;
            }
            rs += __shfl_xor_sync(0xffffffffu, rs, 8);
            rs += __shfl_xor_sync(0xffffffffu, rs, 4);
            rs += __shfl_xor_sync(0xffffffffu, rs, 2);
            rs += __shfl_xor_sync(0xffffffffu, rs, 1);
            l_i[i] = l_i[i] * corr + rs;
            m_i[i] = mnew;
            #pragma unroll
            for (int jj = 0; jj < 8; jj++) o_acc[i][jj] *= corr;
            #pragma unroll
            for (int j = 0; j < 4; j++)
                Ps[(4 * ty + i) * PPAD + 4 * tx + j] = s[i][j];
        }
        __syncthreads();

        #pragma unroll 8
        for (int n = 0; n < 64; n++) {
            float4 v0 = *(const float4*)&Vs[n * HDIM + 8 * tx];
            float4 v1 = *(const float4*)&Vs[n * HDIM + 8 * tx + 4];
            #pragma unroll
            for (int i = 0; i < 4; i++) {
                const float p = Ps[(4 * ty + i) * PPAD + n];
                o_acc[i][0] += p * v0.x;
                o_acc[i][1] += p * v0.y;
                o_acc[i][2] += p * v0.z;
                o_acc[i][3] += p * v0.w;
                o_acc[i][4] += p * v1.x;
                o_acc[i][5] += p * v1.y;
                o_acc[i][6] += p * v1.z;
                o_acc[i][7] += p * v1.w;
            }
        }
    }

    #pragma unroll
    for (int i = 0; i < 4; i++) {
        const float inv = 1.0f / l_i[i];
        const int r = qbase + 4 * ty + i;
        float4 o0 = make_float4(o_acc[i][0] * inv, o_acc[i][1] * inv,
                                o_acc[i][2] * inv, o_acc[i][3] * inv);
        float4 o1 = make_float4(o_acc[i][4] * inv, o_acc[i][5] * inv,
                                o_acc[i][6] * inv, o_acc[i][7] * inv);
        *(float4*)&Og[(size_t)r * DIM + h * HDIM + 8 * tx]     = o0;
        *(float4*)&Og[(size_t)r * DIM + h * HDIM + 8 * tx + 4] = o1;
    }
}

// ============================================================================
// launch
// ============================================================================
static inline void split_launch(const float* src, __nv_bfloat16* hi,
                                __nv_bfloat16* lo, int n)
{
    const int n4 = n / 4;
    split_kernel<<<(n4 + 255) / 256, 256>>>(src, hi, lo, n4);
}

extern "C" void kernel_launch(void* const* d_in, const int* in_sizes, int n_in,
                              void* d_out, int out_size)
{
    (void)in_sizes; (void)n_in; (void)out_size;
    const float* x  = (const float*)d_in[0];
    const float* wq = (const float*)d_in[1];
    const float* wk = (const float*)d_in[2];
    const float* wv = (const float*)d_in[3];
    const float* wo = (const float*)d_in[4];
    const float* fc = (const float*)d_in[5];
    const float* fs = (const float*)d_in[6];
    float* out = (float*)d_out;

    float *xq, *xk, *xv, *attn;
    __nv_bfloat16 *xh, *xl, *wqh, *wql, *wkh, *wkl, *wvh, *wvl, *woh, *wol, *ath, *atl;
    cudaGetSymbolAddress((void**)&xq,   g_xq);
    cudaGetSymbolAddress((void**)&xk,   g_xk);
    cudaGetSymbolAddress((void**)&xv,   g_xv);
    cudaGetSymbolAddress((void**)&attn, g_attn);
    cudaGetSymbolAddress((void**)&xh,  g_xh);  cudaGetSymbolAddress((void**)&xl,  g_xl);
    cudaGetSymbolAddress((void**)&wqh, g_wqh); cudaGetSymbolAddress((void**)&wql, g_wql);
    cudaGetSymbolAddress((void**)&wkh, g_wkh); cudaGetSymbolAddress((void**)&wkl, g_wkl);
    cudaGetSymbolAddress((void**)&wvh, g_wvh); cudaGetSymbolAddress((void**)&wvl, g_wvl);
    cudaGetSymbolAddress((void**)&woh, g_woh); cudaGetSymbolAddress((void**)&wol, g_wol);
    cudaGetSymbolAddress((void**)&ath, g_ath); cudaGetSymbolAddress((void**)&atl, g_atl);

    cudaFuncSetAttribute(gemm_bf16x3_kernel,
                         cudaFuncAttributeMaxDynamicSharedMemorySize, GEMM_SMEM);
    cudaFuncSetAttribute(flash_kernel,
                         cudaFuncAttributeMaxDynamicSharedMemorySize, FLASH_SMEM);

    // 0) split inputs to bf16 hi/lo
    split_launch(x,  xh,  xl,  SEQ * DIM);
    split_launch(wq, wqh, wql, DIM * DIM);
    split_launch(wk, wkh, wkl, KVDIM * DIM);
    split_launch(wv, wvh, wvl, KVDIM * DIM);
    split_launch(wo, woh, wol, DIM * DIM);

    // 1) Q projection
    gemm_bf16x3_kernel<<<dim3(DIM / 128, SEQ / 128, 1), 256, GEMM_SMEM>>>(
        xh, xl, wqh, wql, xq, nullptr, nullptr, nullptr, SEQ, DIM, DIM);

    // 2) K and V projections fused (z = 0 -> K, z = 1 -> V)
    gemm_bf16x3_kernel<<<dim3(KVDIM / 128, SEQ / 128, 2), 256, GEMM_SMEM>>>(
        xh, xl, wkh, wkl, xk, wvh, wvl, xv, SEQ, KVDIM, DIM);

    // 3) RoPE
    {
        const int nq = SEQ * HEADS * (HDIM / 2);
        rope_kernel<<<(nq + 255) / 256, 256>>>(xq, fc, fs, HEADS);
        const int nk = SEQ * KVHEADS * (HDIM / 2);
        rope_kernel<<<(nk + 255) / 256, 256>>>(xk, fc, fs, KVHEADS);
    }

    // 4) flash attention (fp32)
    flash_kernel<<<dim3(SEQ / 64, HEADS), 256, FLASH_SMEM>>>(xq, xk, xv, attn);

    // 5) split attention output, then O projection
    split_launch(attn, ath, atl, SEQ * DIM);
    gemm_bf16x3_kernel<<<dim3(DIM / 128, SEQ / 128, 1), 256, GEMM_SMEM>>>(
        ath, atl, woh, wol, out, nullptr, nullptr, nullptr, SEQ, DIM, DIM);
}

// round 3
// speedup vs baseline: 1.6699x; 1.0604x over previous
#include <cuda_runtime.h>
#include <cuda_bf16.h>
#include <cstdint>
#include <cstddef>

#define DIM     4096
#define SEQ     2048
#define HEADS   32
#define KVHEADS 8
#define HDIM    128
#define KVDIM   1024   // KVHEADS*HDIM

// ------------------------- scratch (static, no allocation) -------------------
__device__ float g_xq[SEQ * DIM];      // fp32 Q proj
__device__ float g_xk[SEQ * KVDIM];
__device__ float g_xv[SEQ * KVDIM];

// bf16 hi/lo splits
__device__ __nv_bfloat16 g_xh[SEQ * DIM],    g_xl[SEQ * DIM];
__device__ __nv_bfloat16 g_wqh[DIM * DIM],   g_wql[DIM * DIM];
__device__ __nv_bfloat16 g_wkh[KVDIM * DIM], g_wkl[KVDIM * DIM];
__device__ __nv_bfloat16 g_wvh[KVDIM * DIM], g_wvl[KVDIM * DIM];
__device__ __nv_bfloat16 g_woh[DIM * DIM],   g_wol[DIM * DIM];
__device__ __nv_bfloat16 g_ath[SEQ * DIM],   g_atl[SEQ * DIM];
__device__ __nv_bfloat16 g_qh[SEQ * DIM],    g_ql[SEQ * DIM];
__device__ __nv_bfloat16 g_kh[SEQ * KVDIM],  g_kl[SEQ * KVDIM];
__device__ __nv_bfloat16 g_vh[SEQ * KVDIM],  g_vl[SEQ * KVDIM];

// ============================================================================
// split: fp32 -> bf16 hi + bf16 lo
// ============================================================================
__global__ void split_kernel(const float* __restrict__ x,
                             __nv_bfloat16* __restrict__ hi,
                             __nv_bfloat16* __restrict__ lo, int n4)
{
    const int i = blockIdx.x * blockDim.x + threadIdx.x;
    if (i >= n4) return;
    float4 v = ((const float4*)x)[i];
    __nv_bfloat16 h0 = __float2bfloat16(v.x);
    __nv_bfloat16 h1 = __float2bfloat16(v.y);
    __nv_bfloat16 h2 = __float2bfloat16(v.z);
    __nv_bfloat16 h3 = __float2bfloat16(v.w);
    __nv_bfloat16 l0 = __float2bfloat16(v.x - __bfloat162float(h0));
    __nv_bfloat16 l1 = __float2bfloat16(v.y - __bfloat162float(h1));
    __nv_bfloat16 l2 = __float2bfloat16(v.z - __bfloat162float(h2));
    __nv_bfloat16 l3 = __float2bfloat16(v.w - __bfloat162float(h3));
    __nv_bfloat162 hp0 = __halves2bfloat162(h0, h1);
    __nv_bfloat162 hp1 = __halves2bfloat162(h2, h3);
    __nv_bfloat162 lp0 = __halves2bfloat162(l0, l1);
    __nv_bfloat162 lp1 = __halves2bfloat162(l2, l3);
    uint2 hv, lv;
    hv.x = *(uint32_t*)&hp0; hv.y = *(uint32_t*)&hp1;
    lv.x = *(uint32_t*)&lp0; lv.y = *(uint32_t*)&lp1;
    ((uint2*)hi)[i] = hv;
    ((uint2*)lo)[i] = lv;
}

// ============================================================================
// RoPE + split: reads fp32 [SEQ][nheads*HDIM], writes rotated bf16 hi/lo
// ============================================================================
__global__ void rope_split_kernel(const float* __restrict__ t,
                                  const float* __restrict__ fc,
                                  const float* __restrict__ fs,
                                  __nv_bfloat16* __restrict__ hi,
                                  __nv_bfloat16* __restrict__ lo,
                                  int nheads)
{
    const int idx = blockIdx.x * blockDim.x + threadIdx.x;
    const int total = SEQ * nheads * (HDIM / 2);
    if (idx >= total) return;
    const int p  = idx & 63;
    const int t2 = idx >> 6;
    const int hh = t2 % nheads;
    const int s  = t2 / nheads;
    const float c  = fc[s * 64 + p];
    const float sn = fs[s * 64 + p];
    const size_t base = ((size_t)s * nheads + hh) * HDIM + 2 * p;
    const float a = t[base];
    const float b = t[base + 1];
    const float ra = a * c - b * sn;
    const float rb = a * sn + b * c;
    __nv_bfloat16 ha = __float2bfloat16(ra);
    __nv_bfloat16 hb = __float2bfloat16(rb);
    __nv_bfloat16 la = __float2bfloat16(ra - __bfloat162float(ha));
    __nv_bfloat16 lb = __float2bfloat16(rb - __bfloat162float(hb));
    __nv_bfloat162 hp = __halves2bfloat162(ha, hb);
    __nv_bfloat162 lp = __halves2bfloat162(la, lb);
    *(uint32_t*)&hi[base] = *(uint32_t*)&hp;
    *(uint32_t*)&lo[base] = *(uint32_t*)&lp;
}

// ============================================================================
// shared mma helpers
// ============================================================================
__device__ __forceinline__ void ldsm4(uint32_t* r, uint32_t addr) {
    asm volatile("ldmatrix.sync.aligned.m8n8.x4.shared.b16 {%0,%1,%2,%3}, [%4];"
                 : "=r"(r[0]), "=r"(r[1]), "=r"(r[2]), "=r"(r[3]) : "r"(addr));
}
__device__ __forceinline__ void ldsm4t(uint32_t* r, uint32_t addr) {
    asm volatile("ldmatrix.sync.aligned.m8n8.x4.trans.shared.b16 {%0,%1,%2,%3}, [%4];"
                 : "=r"(r[0]), "=r"(r[1]), "=r"(r[2]), "=r"(r[3]) : "r"(addr));
}
__device__ __forceinline__ void mma16816(float* c, const uint32_t* a, const uint32_t* b) {
    asm volatile("mma.sync.aligned.m16n8k16.row.col.f32.bf16.bf16.f32 "
                 "{%0,%1,%2,%3},{%4,%5,%6,%7},{%8,%9},{%0,%1,%2,%3};"
                 : "+f"(c[0]), "+f"(c[1]), "+f"(c[2]), "+f"(c[3])
                 : "r"(a[0]), "r"(a[1]), "r"(a[2]), "r"(a[3]), "r"(b[0]), "r"(b[1]));
}

#define CP16(dst, src) asm volatile("cp.async.cg.shared.global [%0], [%1], 16;" :: "r"(dst), "l"(src))
#define CP_COMMIT()    asm volatile("cp.async.commit_group;")
#define CP_WAIT(n)     asm volatile("cp.async.wait_group %0;" :: "n"(n))

// ============================================================================
// bf16x3 tensor-core GEMM (unchanged from R2)
// ============================================================================
#define GBK 32
#define SMAT 8192
#define SBUF (4 * SMAT)
#define GEMM_SMEM (2 * SBUF)

__device__ __forceinline__ uint32_t soff(int row, int chunk) {
    return (uint32_t)((row << 6) + ((chunk ^ ((row >> 1) & 3)) << 4));
}

__global__ void __launch_bounds__(256, 2) gemm_bf16x3_kernel(
    const __nv_bfloat16* __restrict__ Ah, const __nv_bfloat16* __restrict__ Al,
    const __nv_bfloat16* Bh, const __nv_bfloat16* Bl, float* C,
    const __nv_bfloat16* B2h, const __nv_bfloat16* B2l, float* C2,
    int M, int N, int K)
{
    if (blockIdx.z == 1) { Bh = B2h; Bl = B2l; C = C2; }

    extern __shared__ char smem[];
    const int tid  = threadIdx.x;
    const int lane = tid & 31;
    const int w    = tid >> 5;
    const int wm   = w >> 2;
    const int wn   = w & 3;
    const int bm   = blockIdx.y * 128;
    const int bn   = blockIdx.x * 128;

    const int lrow = tid >> 2;
    const int lc   = tid & 3;

    const __nv_bfloat16* gA[2] = { Ah, Al };
    const __nv_bfloat16* gB[2] = { Bh, Bl };

    float acc[4][4][4];
    #pragma unroll
    for (int i = 0; i < 4; i++)
        #pragma unroll
        for (int j = 0; j < 4; j++)
            #pragma unroll
            for (int r = 0; r < 4; r++) acc[i][j][r] = 0.0f;

    const uint32_t sbase = (uint32_t)__cvta_generic_to_shared(smem);

    auto load_tile = [&](int k0, int b) {
        const uint32_t bufo = sbase + b * SBUF;
        #pragma unroll
        for (int m = 0; m < 2; m++) {
            const __nv_bfloat16* g = gA[m] + (size_t)(bm + lrow) * K + k0 + lc * 8;
            CP16(bufo + m * SMAT + soff(lrow, lc), g);
            CP16(bufo + m * SMAT + soff(lrow + 64, lc), g + (size_t)64 * K);
        }
        #pragma unroll
        for (int m = 0; m < 2; m++) {
            const __nv_bfloat16* g = gB[m] + (size_t)(bn + lrow) * K + k0 + lc * 8;
            CP16(bufo + (2 + m) * SMAT + soff(lrow, lc), g);
            CP16(bufo + (2 + m) * SMAT + soff(lrow + 64, lc), g + (size_t)64 * K);
        }
    };

    const int nIt = K / GBK;
    load_tile(0, 0);
    CP_COMMIT();

    const int rl = lane & 15;
    const int rh = lane >> 4;

    for (int it = 0; it < nIt; ++it) {
        if (it + 1 < nIt) {
            load_tile((it + 1) * GBK, (it + 1) & 1);
            CP_COMMIT();
            CP_WAIT(1);
        } else {
            CP_WAIT(0);
        }
        __syncthreads();

        const uint32_t bufo = sbase + (it & 1) * SBUF;
        const uint32_t sAh = bufo;
        const uint32_t sAl = bufo + SMAT;
        const uint32_t sBh = bufo + 2 * SMAT;
        const uint32_t sBl = bufo + 3 * SMAT;

        #pragma unroll
        for (int ks = 0; ks < 2; ks++) {
            const int chunk = 2 * ks + rh;
            uint32_t ah[4][4], al[4][4], bh[4][2], bl[4][2];

            #pragma unroll
            for (int mi = 0; mi < 4; mi++)
                ldsm4(ah[mi], sAh + soff(wm * 64 + mi * 16 + rl, chunk));
            #pragma unroll
            for (int nb = 0; nb < 2; nb++) {
                uint32_t r4[4];
                ldsm4(r4, sBh + soff(wn * 32 + nb * 16 + rl, chunk));
                bh[2 * nb][0] = r4[0]; bh[2 * nb + 1][0] = r4[1];
                bh[2 * nb][1] = r4[2]; bh[2 * nb + 1][1] = r4[3];
            }
            #pragma unroll
            for (int mi = 0; mi < 4; mi++)
                #pragma unroll
                for (int nj = 0; nj < 4; nj++)
                    mma16816(acc[mi][nj], ah[mi], bh[nj]);

            #pragma unroll
            for (int nb = 0; nb < 2; nb++) {
                uint32_t r4[4];
                ldsm4(r4, sBl + soff(wn * 32 + nb * 16 + rl, chunk));
                bl[2 * nb][0] = r4[0]; bl[2 * nb + 1][0] = r4[1];
                bl[2 * nb][1] = r4[2]; bl[2 * nb + 1][1] = r4[3];
            }
            #pragma unroll
            for (int mi = 0; mi < 4; mi++)
                #pragma unroll
                for (int nj = 0; nj < 4; nj++)
                    mma16816(acc[mi][nj], ah[mi], bl[nj]);

            #pragma unroll
            for (int mi = 0; mi < 4; mi++)
                ldsm4(al[mi], sAl + soff(wm * 64 + mi * 16 + rl, chunk));
            #pragma unroll
            for (int mi = 0; mi < 4; mi++)
                #pragma unroll
                for (int nj = 0; nj < 4; nj++)
                    mma16816(acc[mi][nj], al[mi], bh[nj]);
        }
        __syncthreads();
    }

    const int tg = lane >> 2;
    const int ti = lane & 3;
    #pragma unroll
    for (int mi = 0; mi < 4; mi++) {
        const int row = bm + wm * 64 + mi * 16 + tg;
        #pragma unroll
        for (int nj = 0; nj < 4; nj++) {
            const int col = bn + wn * 32 + nj * 8 + 2 * ti;
            float2 v0 = make_float2(acc[mi][nj][0], acc[mi][nj][1]);
            float2 v1 = make_float2(acc[mi][nj][2], acc[mi][nj][3]);
            *(float2*)&C[(size_t)row * N + col]       = v0;
            *(float2*)&C[(size_t)(row + 8) * N + col] = v1;
        }
    }
}

// ============================================================================
// Tensor-core flash attention, bf16x3, causal, GQA.
// CTA = (head, 128 q rows). 8 warps x 16 rows. kv tiles of 64, double-buffered
// cp.async. Q hi/lo resident in smem. P split hi/lo in registers; acc layout
// feeds PV A-fragments directly.
// ============================================================================
#define BQ 128
#define BKV 64
#define QMAT 32768              // 128 rows x 256B
#define KVMAT 16384             // 64 rows x 256B
#define FSTAGE (4 * KVMAT)      // Kh,Kl,Vh,Vl
#define FLASH_SMEM (2 * QMAT + 2 * FSTAGE)   // 196608

__device__ __forceinline__ uint32_t fsw(int r, int c) {
    return (uint32_t)((r << 8) + ((c ^ (r & 7)) << 4));
}

__device__ __forceinline__ uint32_t pack_hi_rz(float p0, float p1, float& lo0, float& lo1) {
    uint32_t u0 = __float_as_uint(p0), u1 = __float_as_uint(p1);
    lo0 = p0 - __uint_as_float(u0 & 0xffff0000u);
    lo1 = p1 - __uint_as_float(u1 & 0xffff0000u);
    return __byte_perm(u0, u1, 0x7632);
}
__device__ __forceinline__ uint32_t pack_rn(float a, float b) {
    __nv_bfloat162 t = __floats2bfloat162_rn(a, b);
    return *(uint32_t*)&t;
}

__global__ void __launch_bounds__(256, 1) flash_tc_kernel(
    const __nv_bfloat16* __restrict__ qh, const __nv_bfloat16* __restrict__ ql,
    const __nv_bfloat16* __restrict__ kh, const __nv_bfloat16* __restrict__ kl,
    const __nv_bfloat16* __restrict__ vh, const __nv_bfloat16* __restrict__ vl,
    __nv_bfloat16* __restrict__ ath, __nv_bfloat16* __restrict__ atl)
{
    extern __shared__ char smc[];
    const uint32_t sb  = (uint32_t)__cvta_generic_to_shared(smc);
    const uint32_t sQh = sb, sQl = sb + QMAT;

    const int tid  = threadIdx.x;
    const int lane = tid & 31;
    const int w    = tid >> 5;
    const int rl   = lane & 15;
    const int rh   = lane >> 4;
    const int tg   = lane >> 2;
    const int ti   = lane & 3;
    const int vro  = (lane & 7) + ((lane >> 3) & 1) * 8;  // trans-ldsm row offset
    const int vco  = lane >> 4;                           // trans-ldsm chunk offset

    const int qt    = gridDim.x - 1 - blockIdx.x;
    const int h     = blockIdx.y;
    const int kvh   = h >> 2;
    const int qbase = qt * BQ;
    const int wrow  = w * 16;

    // load Q hi/lo (resident)
    for (int f = tid; f < 2048; f += 256) {
        const int r = f >> 4, c = f & 15;
        const size_t go = (size_t)(qbase + r) * DIM + h * HDIM + c * 8;
        CP16(sQh + fsw(r, c), qh + go);
        CP16(sQl + fsw(r, c), ql + go);
    }
    CP_COMMIT();

    auto loadKV = [&](int kt) {
        const uint32_t base = sb + 2 * QMAT + (kt & 1) * FSTAGE;
        const int kvb = kt * BKV;
        for (int f = tid; f < 1024; f += 256) {
            const int r = f >> 4, c = f & 15;
            const size_t go = (size_t)(kvb + r) * KVDIM + kvh * HDIM + c * 8;
            const uint32_t so = fsw(r, c);
            CP16(base + so,             kh + go);
            CP16(base + KVMAT + so,     kl + go);
            CP16(base + 2 * KVMAT + so, vh + go);
            CP16(base + 3 * KVMAT + so, vl + go);
        }
    };

    loadKV(0);
    CP_COMMIT();

    float o[16][4];
    #pragma unroll
    for (int i = 0; i < 16; i++)
        #pragma unroll
        for (int r = 0; r < 4; r++) o[i][r] = 0.0f;
    float m0 = -1e30f, m1 = -1e30f, l0 = 0.0f, l1 = 0.0f;
    const float scale = 0.08838834764831843f;
    const int row0 = qbase + wrow + tg;
    const int row1 = row0 + 8;

    const int nkt = 2 * qt + 2;
    for (int kt = 0; kt < nkt; kt++) {
        if (kt + 1 < nkt) { loadKV(kt + 1); CP_COMMIT(); CP_WAIT(1); }
        else              { CP_WAIT(0); }
        __syncthreads();

        const uint32_t base = sb + 2 * QMAT + (kt & 1) * FSTAGE;
        const uint32_t sKh = base, sKl = base + KVMAT;
        const uint32_t sVh = base + 2 * KVMAT, sVl = base + 3 * KVMAT;
        const int kvb = kt * BKV;

        // ---- S = Q K^T (3-pass bf16x3) ----
        float s[8][4];
        #pragma unroll
        for (int i = 0; i < 8; i++)
            #pragma unroll
            for (int r = 0; r < 4; r++) s[i][r] = 0.0f;

        #pragma unroll
        for (int kc = 0; kc < 8; kc++) {
            uint32_t ah[4], al[4];
            ldsm4(ah, sQh + fsw(wrow + rl, 2 * kc + rh));
            ldsm4(al, sQl + fsw(wrow + rl, 2 * kc + rh));
            #pragma unroll
            for (int nb = 0; nb < 4; nb++) {
                uint32_t rk[4], rkl[4];
                ldsm4(rk,  sKh + fsw(nb * 16 + rl, 2 * kc + rh));
                ldsm4(rkl, sKl + fsw(nb * 16 + rl, 2 * kc + rh));
                uint32_t b0[2] = { rk[0], rk[2] },  b1[2] = { rk[1], rk[3] };
                uint32_t c0[2] = { rkl[0], rkl[2] }, c1[2] = { rkl[1], rkl[3] };
                mma16816(s[2 * nb],     ah, b0);
                mma16816(s[2 * nb + 1], ah, b1);
                mma16816(s[2 * nb],     ah, c0);
                mma16816(s[2 * nb + 1], ah, c1);
                mma16816(s[2 * nb],     al, b0);
                mma16816(s[2 * nb + 1], al, b1);
            }
        }

        // ---- scale + causal mask ----
        const bool needmask = (kt >= 2 * qt);
        #pragma unroll
        for (int nj = 0; nj < 8; nj++) {
            #pragma unroll
            for (int r = 0; r < 4; r++) {
                float v = s[nj][r] * scale;
                if (needmask) {
                    const int col = kvb + nj * 8 + 2 * ti + (r & 1);
                    const int row = (r & 2) ? row1 : row0;
                    if (col > row) v = -1e30f;
                }
                s[nj][r] = v;
            }
        }

        // ---- online softmax ----
        float mx0 = -1e30f, mx1 = -1e30f;
        #pragma unroll
        for (int nj = 0; nj < 8; nj++) {
            mx0 = fmaxf(mx0, fmaxf(s[nj][0], s[nj][1]));
            mx1 = fmaxf(mx1, fmaxf(s[nj][2], s[nj][3]));
        }
        mx0 = fmaxf(mx0, __shfl_xor_sync(0xffffffffu, mx0, 1));
        mx0 = fmaxf(mx0, __shfl_xor_sync(0xffffffffu, mx0, 2));
        mx1 = fmaxf(mx1, __shfl_xor_sync(0xffffffffu, mx1, 1));
        mx1 = fmaxf(mx1, __shfl_xor_sync(0xffffffffu, mx1, 2));
        const float mn0 = fmaxf(m0, mx0), mn1 = fmaxf(m1, mx1);
        const float cr0 = __expf(m0 - mn0), cr1 = __expf(m1 - mn1);
        m0 = mn0; m1 = mn1;

        float sum0 = 0.0f, sum1 = 0.0f;
        #pragma unroll
        for (int nj = 0; nj < 8; nj++) {
            s[nj][0] = __expf(s[nj][0] - mn0); sum0 += s[nj][0];
            s[nj][1] = __expf(s[nj][1] - mn0); sum0 += s[nj][1];
            s[nj][2] = __expf(s[nj][2] - mn1); sum1 += s[nj][2];
            s[nj][3] = __expf(s[nj][3] - mn1); sum1 += s[nj][3];
        }
        sum0 += __shfl_xor_sync(0xffffffffu, sum0, 1);
        sum0 += __shfl_xor_sync(0xffffffffu, sum0, 2);
        sum1 += __shfl_xor_sync(0xffffffffu, sum1, 1);
        sum1 += __shfl_xor_sync(0xffffffffu, sum1, 2);
        l0 = l0 * cr0 + sum0;
        l1 = l1 * cr1 + sum1;

        #pragma unroll
        for (int nj = 0; nj < 16; nj++) {
            o[nj][0] *= cr0; o[nj][1] *= cr0;
            o[nj][2] *= cr1; o[nj][3] *= cr1;
        }

        // ---- O += P V (3-pass) ----
        #pragma unroll
        for (int kc = 0; kc < 4; kc++) {
            uint32_t pah[4], pal[4];
            {
                float la, lb;
                pah[0] = pack_hi_rz(s[2 * kc][0],     s[2 * kc][1],     la, lb); pal[0] = pack_rn(la, lb);
                pah[1] = pack_hi_rz(s[2 * kc][2],     s[2 * kc][3],     la, lb); pal[1] = pack_rn(la, lb);
                pah[2] = pack_hi_rz(s[2 * kc + 1][0], s[2 * kc + 1][1], la, lb); pal[2] = pack_rn(la, lb);
                pah[3] = pack_hi_rz(s[2 * kc + 1][2], s[2 * kc + 1][3], la, lb); pal[3] = pack_rn(la, lb);
            }
            #pragma unroll
            for (int nb = 0; nb < 8; nb++) {
                uint32_t rv[4], rw[4];
                const uint32_t so = fsw(kc * 16 + vro, 2 * nb + vco);
                ldsm4t(rv, sVh + so);
                ldsm4t(rw, sVl + so);
                uint32_t b0[2] = { rv[0], rv[1] }, b1[2] = { rv[2], rv[3] };
                uint32_t c0[2] = { rw[0], rw[1] }, c1[2] = { rw[2], rw[3] };
                mma16816(o[2 * nb],     pah, b0);
                mma16816(o[2 * nb + 1], pah, b1);
                mma16816(o[2 * nb],     pah, c0);
                mma16816(o[2 * nb + 1], pah, c1);
                mma16816(o[2 * nb],     pal, b0);
                mma16816(o[2 * nb + 1], pal, b1);
            }
        }
        __syncthreads();
    }

    // ---- epilogue: normalize, split hi/lo, store ----
    const float inv0 = 1.0f / l0, inv1 = 1.0f / l1;
    #pragma unroll
    for (int nj = 0; nj < 16; nj++) {
        const int col = h * HDIM + nj * 8 + 2 * ti;
        float v0 = o[nj][0] * inv0, v1 = o[nj][1] * inv0;
        float v2 = o[nj][2] * inv1, v3 = o[nj][3] * inv1;
        __nv_bfloat162 h0 = __floats2bfloat162_rn(v0, v1);
        __nv_bfloat162 h1 = __floats2bfloat162_rn(v2, v3);
        __nv_bfloat162 e0 = __floats2bfloat162_rn(v0 - __low2float(h0), v1 - __high2float(h0));
        __nv_bfloat162 e1 = __floats2bfloat162_rn(v2 - __low2float(h1), v3 - __high2float(h1));
        *(uint32_t*)&ath[(size_t)row0 * DIM + col] = *(uint32_t*)&h0;
        *(uint32_t*)&ath[(size_t)row1 * DIM + col] = *(uint32_t*)&h1;
        *(uint32_t*)&atl[(size_t)row0 * DIM + col] = *(uint32_t*)&e0;
        *(uint32_t*)&atl[(size_t)row1 * DIM + col] = *(uint32_t*)&e1;
    }
}

// ============================================================================
// launch
// ============================================================================
static inline void split_launch(const float* src, __nv_bfloat16* hi,
                                __nv_bfloat16* lo, int n)
{
    const int n4 = n / 4;
    split_kernel<<<(n4 + 255) / 256, 256>>>(src, hi, lo, n4);
}

extern "C" void kernel_launch(void* const* d_in, const int* in_sizes, int n_in,
                              void* d_out, int out_size)
{
    (void)in_sizes; (void)n_in; (void)out_size;
    const float* x  = (const float*)d_in[0];
    const float* wq = (const float*)d_in[1];
    const float* wk = (const float*)d_in[2];
    const float* wv = (const float*)d_in[3];
    const float* wo = (const float*)d_in[4];
    const float* fc = (const float*)d_in[5];
    const float* fs = (const float*)d_in[6];
    float* out = (float*)d_out;

    float *xq, *xk, *xv;
    __nv_bfloat16 *xh, *xl, *wqh, *wql, *wkh, *wkl, *wvh, *wvl, *woh, *wol;
    __nv_bfloat16 *ath, *atl, *qh, *ql, *kh, *kl, *vh, *vl;
    cudaGetSymbolAddress((void**)&xq, g_xq);
    cudaGetSymbolAddress((void**)&xk, g_xk);
    cudaGetSymbolAddress((void**)&xv, g_xv);
    cudaGetSymbolAddress((void**)&xh,  g_xh);  cudaGetSymbolAddress((void**)&xl,  g_xl);
    cudaGetSymbolAddress((void**)&wqh, g_wqh); cudaGetSymbolAddress((void**)&wql, g_wql);
    cudaGetSymbolAddress((void**)&wkh, g_wkh); cudaGetSymbolAddress((void**)&wkl, g_wkl);
    cudaGetSymbolAddress((void**)&wvh, g_wvh); cudaGetSymbolAddress((void**)&wvl, g_wvl);
    cudaGetSymbolAddress((void**)&woh, g_woh); cudaGetSymbolAddress((void**)&wol, g_wol);
    cudaGetSymbolAddress((void**)&ath, g_ath); cudaGetSymbolAddress((void**)&atl, g_atl);
    cudaGetSymbolAddress((void**)&qh,  g_qh);  cudaGetSymbolAddress((void**)&ql,  g_ql);
    cudaGetSymbolAddress((void**)&kh,  g_kh);  cudaGetSymbolAddress((void**)&kl,  g_kl);
    cudaGetSymbolAddress((void**)&vh,  g_vh);  cudaGetSymbolAddress((void**)&vl,  g_vl);

    cudaFuncSetAttribute(gemm_bf16x3_kernel,
                         cudaFuncAttributeMaxDynamicSharedMemorySize, GEMM_SMEM);
    cudaFuncSetAttribute(flash_tc_kernel,
                         cudaFuncAttributeMaxDynamicSharedMemorySize, FLASH_SMEM);

    // 0) split inputs to bf16 hi/lo
    split_launch(x,  xh,  xl,  SEQ * DIM);
    split_launch(wq, wqh, wql, DIM * DIM);
    split_launch(wk, wkh, wkl, KVDIM * DIM);
    split_launch(wv, wvh, wvl, KVDIM * DIM);
    split_launch(wo, woh, wol, DIM * DIM);

    // 1) Q projection (fp32 out)
    gemm_bf16x3_kernel<<<dim3(DIM / 128, SEQ / 128, 1), 256, GEMM_SMEM>>>(
        xh, xl, wqh, wql, xq, nullptr, nullptr, nullptr, SEQ, DIM, DIM);

    // 2) K and V projections fused
    gemm_bf16x3_kernel<<<dim3(KVDIM / 128, SEQ / 128, 2), 256, GEMM_SMEM>>>(
        xh, xl, wkh, wkl, xk, wvh, wvl, xv, SEQ, KVDIM, DIM);

    // 3) RoPE + split to bf16 hi/lo; split V
    {
        const int nq = SEQ * HEADS * (HDIM / 2);
        rope_split_kernel<<<(nq + 255) / 256, 256>>>(xq, fc, fs, qh, ql, HEADS);
        const int nk = SEQ * KVHEADS * (HDIM / 2);
        rope_split_kernel<<<(nk + 255) / 256, 256>>>(xk, fc, fs, kh, kl, KVHEADS);
        split_launch(xv, vh, vl, SEQ * KVDIM);
    }

    // 4) tensor-core flash attention -> attn hi/lo
    flash_tc_kernel<<<dim3(SEQ / BQ, HEADS), 256, FLASH_SMEM>>>(
        qh, ql, kh, kl, vh, vl, ath, atl);

    // 5) O projection
    gemm_bf16x3_kernel<<<dim3(DIM / 128, SEQ / 128, 1), 256, GEMM_SMEM>>>(
        ath, atl, woh, wol, out, nullptr, nullptr, nullptr, SEQ, DIM, DIM);
}

// round 5
// speedup vs baseline: 2.5668x; 1.5371x over previous
#include <cuda_runtime.h>
#include <cuda_bf16.h>
#include <cstdint>
#include <cstddef>

#define DIM     4096
#define SEQ     2048
#define HEADS   32
#define KVHEADS 8
#define HDIM    128
#define KVDIM   1024   // KVHEADS*HDIM

// ------------------------- scratch (static, no allocation) -------------------
__device__ float g_xq[SEQ * DIM];      // fp32 Q proj
__device__ float g_xk[SEQ * KVDIM];
__device__ float g_xv[SEQ * KVDIM];

// bf16 hi/lo splits
__device__ __nv_bfloat16 g_xh[SEQ * DIM],    g_xl[SEQ * DIM];
__device__ __nv_bfloat16 g_wqh[DIM * DIM],   g_wql[DIM * DIM];
__device__ __nv_bfloat16 g_wkh[KVDIM * DIM], g_wkl[KVDIM * DIM];
__device__ __nv_bfloat16 g_wvh[KVDIM * DIM], g_wvl[KVDIM * DIM];
__device__ __nv_bfloat16 g_woh[DIM * DIM],   g_wol[DIM * DIM];
__device__ __nv_bfloat16 g_ath[SEQ * DIM],   g_atl[SEQ * DIM];
__device__ __nv_bfloat16 g_qh[SEQ * DIM],    g_ql[SEQ * DIM];
__device__ __nv_bfloat16 g_kh[SEQ * KVDIM],  g_kl[SEQ * KVDIM];
__device__ __nv_bfloat16 g_vh[SEQ * KVDIM],  g_vl[SEQ * KVDIM];

// ============================================================================
// split: fp32 -> bf16 hi + bf16 lo
// ============================================================================
__global__ void split_kernel(const float* __restrict__ x,
                             __nv_bfloat16* __restrict__ hi,
                             __nv_bfloat16* __restrict__ lo, int n4)
{
    const int i = blockIdx.x * blockDim.x + threadIdx.x;
    if (i >= n4) return;
    float4 v = ((const float4*)x)[i];
    __nv_bfloat16 h0 = __float2bfloat16(v.x);
    __nv_bfloat16 h1 = __float2bfloat16(v.y);
    __nv_bfloat16 h2 = __float2bfloat16(v.z);
    __nv_bfloat16 h3 = __float2bfloat16(v.w);
    __nv_bfloat16 l0 = __float2bfloat16(v.x - __bfloat162float(h0));
    __nv_bfloat16 l1 = __float2bfloat16(v.y - __bfloat162float(h1));
    __nv_bfloat16 l2 = __float2bfloat16(v.z - __bfloat162float(h2));
    __nv_bfloat16 l3 = __float2bfloat16(v.w - __bfloat162float(h3));
    __nv_bfloat162 hp0 = __halves2bfloat162(h0, h1);
    __nv_bfloat162 hp1 = __halves2bfloat162(h2, h3);
    __nv_bfloat162 lp0 = __halves2bfloat162(l0, l1);
    __nv_bfloat162 lp1 = __halves2bfloat162(l2, l3);
    uint2 hv, lv;
    hv.x = *(uint32_t*)&hp0; hv.y = *(uint32_t*)&hp1;
    lv.x = *(uint32_t*)&lp0; lv.y = *(uint32_t*)&lp1;
    ((uint2*)hi)[i] = hv;
    ((uint2*)lo)[i] = lv;
}

// ============================================================================
// RoPE + split: reads fp32 [SEQ][nheads*HDIM], writes rotated bf16 hi/lo
// ============================================================================
__global__ void rope_split_kernel(const float* __restrict__ t,
                                  const float* __restrict__ fc,
                                  const float* __restrict__ fs,
                                  __nv_bfloat16* __restrict__ hi,
                                  __nv_bfloat16* __restrict__ lo,
                                  int nheads)
{
    const int idx = blockIdx.x * blockDim.x + threadIdx.x;
    const int total = SEQ * nheads * (HDIM / 2);
    if (idx >= total) return;
    const int p  = idx & 63;
    const int t2 = idx >> 6;
    const int hh = t2 % nheads;
    const int s  = t2 / nheads;
    const float c  = fc[s * 64 + p];
    const float sn = fs[s * 64 + p];
    const size_t base = ((size_t)s * nheads + hh) * HDIM + 2 * p;
    const float a = t[base];
    const float b = t[base + 1];
    const float ra = a * c - b * sn;
    const float rb = a * sn + b * c;
    __nv_bfloat16 ha = __float2bfloat16(ra);
    __nv_bfloat16 hb = __float2bfloat16(rb);
    __nv_bfloat16 la = __float2bfloat16(ra - __bfloat162float(ha));
    __nv_bfloat16 lb = __float2bfloat16(rb - __bfloat162float(hb));
    __nv_bfloat162 hp = __halves2bfloat162(ha, hb);
    __nv_bfloat162 lp = __halves2bfloat162(la, lb);
    *(uint32_t*)&hi[base] = *(uint32_t*)&hp;
    *(uint32_t*)&lo[base] = *(uint32_t*)&lp;
}

// ============================================================================
// shared mma helpers
// ============================================================================
__device__ __forceinline__ void ldsm4(uint32_t* r, uint32_t addr) {
    asm volatile("ldmatrix.sync.aligned.m8n8.x4.shared.b16 {%0,%1,%2,%3}, [%4];"
                 : "=r"(r[0]), "=r"(r[1]), "=r"(r[2]), "=r"(r[3]) : "r"(addr));
}
__device__ __forceinline__ void ldsm4t(uint32_t* r, uint32_t addr) {
    asm volatile("ldmatrix.sync.aligned.m8n8.x4.trans.shared.b16 {%0,%1,%2,%3}, [%4];"
                 : "=r"(r[0]), "=r"(r[1]), "=r"(r[2]), "=r"(r[3]) : "r"(addr));
}
__device__ __forceinline__ void mma16816(float* c, const uint32_t* a, const uint32_t* b) {
    asm volatile("mma.sync.aligned.m16n8k16.row.col.f32.bf16.bf16.f32 "
                 "{%0,%1,%2,%3},{%4,%5,%6,%7},{%8,%9},{%0,%1,%2,%3};"
                 : "+f"(c[0]), "+f"(c[1]), "+f"(c[2]), "+f"(c[3])
                 : "r"(a[0]), "r"(a[1]), "r"(a[2]), "r"(a[3]), "r"(b[0]), "r"(b[1]));
}

#define CP16(dst, src) asm volatile("cp.async.cg.shared.global [%0], [%1], 16;" :: "r"(dst), "l"(src))
#define CP_COMMIT()    asm volatile("cp.async.commit_group;")
#define CP_WAIT(n)     asm volatile("cp.async.wait_group %0;" :: "n"(n))

// ============================================================================
// bf16x3 tensor-core GEMM:  C[M,N](fp32) = A[M,K] * B[N,K]^T
// 128x128x32 CTA tile, 256 thr, warp tile 64x32, cp.async double-buffered.
// z==1 switches to (B2,C2).
// ============================================================================
#define GBK 32
#define SMAT 8192
#define SBUF (4 * SMAT)
#define GEMM_SMEM (2 * SBUF)

__device__ __forceinline__ uint32_t soff(int row, int chunk) {
    return (uint32_t)((row << 6) + ((chunk ^ ((row >> 1) & 3)) << 4));
}

__global__ void __launch_bounds__(256, 2) gemm_bf16x3_kernel(
    const __nv_bfloat16* __restrict__ Ah, const __nv_bfloat16* __restrict__ Al,
    const __nv_bfloat16* Bh, const __nv_bfloat16* Bl, float* C,
    const __nv_bfloat16* B2h, const __nv_bfloat16* B2l, float* C2,
    int M, int N, int K)
{
    if (blockIdx.z == 1) { Bh = B2h; Bl = B2l; C = C2; }

    extern __shared__ char smem[];
    const int tid  = threadIdx.x;
    const int lane = tid & 31;
    const int w    = tid >> 5;
    const int wm   = w >> 2;
    const int wn   = w & 3;
    const int bm   = blockIdx.y * 128;
    const int bn   = blockIdx.x * 128;

    const int lrow = tid >> 2;
    const int lc   = tid & 3;

    const __nv_bfloat16* gA[2] = { Ah, Al };
    const __nv_bfloat16* gB[2] = { Bh, Bl };

    float acc[4][4][4];
    #pragma unroll
    for (int i = 0; i < 4; i++)
        #pragma unroll
        for (int j = 0; j < 4; j++)
            #pragma unroll
            for (int r = 0; r < 4; r++) acc[i][j][r] = 0.0f;

    const uint32_t sbase = (uint32_t)__cvta_generic_to_shared(smem);

    auto load_tile = [&](int k0, int b) {
        const uint32_t bufo = sbase + b * SBUF;
        #pragma unroll
        for (int m = 0; m < 2; m++) {
            const __nv_bfloat16* g = gA[m] + (size_t)(bm + lrow) * K + k0 + lc * 8;
            CP16(bufo + m * SMAT + soff(lrow, lc), g);
            CP16(bufo + m * SMAT + soff(lrow + 64, lc), g + (size_t)64 * K);
        }
        #pragma unroll
        for (int m = 0; m < 2; m++) {
            const __nv_bfloat16* g = gB[m] + (size_t)(bn + lrow) * K + k0 + lc * 8;
            CP16(bufo + (2 + m) * SMAT + soff(lrow, lc), g);
            CP16(bufo + (2 + m) * SMAT + soff(lrow + 64, lc), g + (size_t)64 * K);
        }
    };

    const int nIt = K / GBK;
    load_tile(0, 0);
    CP_COMMIT();

    const int rl = lane & 15;
    const int rh = lane >> 4;

    for (int it = 0; it < nIt; ++it) {
        if (it + 1 < nIt) {
            load_tile((it + 1) * GBK, (it + 1) & 1);
            CP_COMMIT();
            CP_WAIT(1);
        } else {
            CP_WAIT(0);
        }
        __syncthreads();

        const uint32_t bufo = sbase + (it & 1) * SBUF;
        const uint32_t sAh = bufo;
        const uint32_t sAl = bufo + SMAT;
        const uint32_t sBh = bufo + 2 * SMAT;
        const uint32_t sBl = bufo + 3 * SMAT;

        #pragma unroll
        for (int ks = 0; ks < 2; ks++) {
            const int chunk = 2 * ks + rh;
            uint32_t ah[4][4], al[4][4], bh[4][2], bl[4][2];

            #pragma unroll
            for (int mi = 0; mi < 4; mi++)
                ldsm4(ah[mi], sAh + soff(wm * 64 + mi * 16 + rl, chunk));
            #pragma unroll
            for (int nb = 0; nb < 2; nb++) {
                uint32_t r4[4];
                ldsm4(r4, sBh + soff(wn * 32 + nb * 16 + rl, chunk));
                bh[2 * nb][0] = r4[0]; bh[2 * nb + 1][0] = r4[1];
                bh[2 * nb][1] = r4[2]; bh[2 * nb + 1][1] = r4[3];
            }
            #pragma unroll
            for (int mi = 0; mi < 4; mi++)
                #pragma unroll
                for (int nj = 0; nj < 4; nj++)
                    mma16816(acc[mi][nj], ah[mi], bh[nj]);

            #pragma unroll
            for (int nb = 0; nb < 2; nb++) {
                uint32_t r4[4];
                ldsm4(r4, sBl + soff(wn * 32 + nb * 16 + rl, chunk));
                bl[2 * nb][0] = r4[0]; bl[2 * nb + 1][0] = r4[1];
                bl[2 * nb][1] = r4[2]; bl[2 * nb + 1][1] = r4[3];
            }
            #pragma unroll
            for (int mi = 0; mi < 4; mi++)
                #pragma unroll
                for (int nj = 0; nj < 4; nj++)
                    mma16816(acc[mi][nj], ah[mi], bl[nj]);

            #pragma unroll
            for (int mi = 0; mi < 4; mi++)
                ldsm4(al[mi], sAl + soff(wm * 64 + mi * 16 + rl, chunk));
            #pragma unroll
            for (int mi = 0; mi < 4; mi++)
                #pragma unroll
                for (int nj = 0; nj < 4; nj++)
                    mma16816(acc[mi][nj], al[mi], bh[nj]);
        }
        __syncthreads();
    }

    const int tg = lane >> 2;
    const int ti = lane & 3;
    #pragma unroll
    for (int mi = 0; mi < 4; mi++) {
        const int row = bm + wm * 64 + mi * 16 + tg;
        #pragma unroll
        for (int nj = 0; nj < 4; nj++) {
            const int col = bn + wn * 32 + nj * 8 + 2 * ti;
            float2 v0 = make_float2(acc[mi][nj][0], acc[mi][nj][1]);
            float2 v1 = make_float2(acc[mi][nj][2], acc[mi][nj][3]);
            *(float2*)&C[(size_t)row * N + col]       = v0;
            *(float2*)&C[(size_t)(row + 8) * N + col] = v1;
        }
    }
}

// ============================================================================
// Tensor-core flash attention, bf16x3, causal, GQA.
// PASS-MAJOR MMA schedule: per pass, all accumulators issue independently,
// eliminating the 3-deep per-accumulator HMMA dependency chains of R3.
// ============================================================================
#define BQ 128
#define BKV 64
#define QMAT 32768
#define KVMAT 16384
#define FSTAGE (4 * KVMAT)
#define FLASH_SMEM (2 * QMAT + 2 * FSTAGE)

__device__ __forceinline__ uint32_t fsw(int r, int c) {
    return (uint32_t)((r << 8) + ((c ^ (r & 7)) << 4));
}
__device__ __forceinline__ uint32_t pack_hi_rz(float p0, float p1, float& lo0, float& lo1) {
    uint32_t u0 = __float_as_uint(p0), u1 = __float_as_uint(p1);
    lo0 = p0 - __uint_as_float(u0 & 0xffff0000u);
    lo1 = p1 - __uint_as_float(u1 & 0xffff0000u);
    return __byte_perm(u0, u1, 0x7632);
}
__device__ __forceinline__ uint32_t pack_rn(float a, float b) {
    __nv_bfloat162 t = __floats2bfloat162_rn(a, b);
    return *(uint32_t*)&t;
}

__global__ void __launch_bounds__(256, 1) flash_tc_kernel(
    const __nv_bfloat16* __restrict__ qh, const __nv_bfloat16* __restrict__ ql,
    const __nv_bfloat16* __restrict__ kh, const __nv_bfloat16* __restrict__ kl,
    const __nv_bfloat16* __restrict__ vh, const __nv_bfloat16* __restrict__ vl,
    __nv_bfloat16* __restrict__ ath, __nv_bfloat16* __restrict__ atl)
{
    extern __shared__ char smc[];
    const uint32_t sb  = (uint32_t)__cvta_generic_to_shared(smc);
    const uint32_t sQh = sb, sQl = sb + QMAT;

    const int tid  = threadIdx.x;
    const int lane = tid & 31;
    const int w    = tid >> 5;
    const int rl   = lane & 15;
    const int rh   = lane >> 4;
    const int tg   = lane >> 2;
    const int ti   = lane & 3;
    const int vro  = (lane & 7) + ((lane >> 3) & 1) * 8;
    const int vco  = lane >> 4;

    const int qt    = gridDim.x - 1 - blockIdx.x;
    const int h     = blockIdx.y;
    const int kvh   = h >> 2;
    const int qbase = qt * BQ;
    const int wrow  = w * 16;

    for (int f = tid; f < 2048; f += 256) {
        const int r = f >> 4, c = f & 15;
        const size_t go = (size_t)(qbase + r) * DIM + h * HDIM + c * 8;
        CP16(sQh + fsw(r, c), qh + go);
        CP16(sQl + fsw(r, c), ql + go);
    }
    CP_COMMIT();

    auto loadKV = [&](int kt) {
        const uint32_t base = sb + 2 * QMAT + (kt & 1) * FSTAGE;
        const int kvb = kt * BKV;
        for (int f = tid; f < 1024; f += 256) {
            const int r = f >> 4, c = f & 15;
            const size_t go = (size_t)(kvb + r) * KVDIM + kvh * HDIM + c * 8;
            const uint32_t so = fsw(r, c);
            CP16(base + so,             kh + go);
            CP16(base + KVMAT + so,     kl + go);
            CP16(base + 2 * KVMAT + so, vh + go);
            CP16(base + 3 * KVMAT + so, vl + go);
        }
    };

    loadKV(0);
    CP_COMMIT();

    float o[16][4];
    #pragma unroll
    for (int i = 0; i < 16; i++)
        #pragma unroll
        for (int r = 0; r < 4; r++) o[i][r] = 0.0f;
    float m0 = -1e30f, m1 = -1e30f, l0 = 0.0f, l1 = 0.0f;
    const float scale = 0.08838834764831843f;
    const int row0 = qbase + wrow + tg;
    const int row1 = row0 + 8;

    const int nkt = 2 * qt + 2;
    for (int kt = 0; kt < nkt; kt++) {
        if (kt + 1 < nkt) { loadKV(kt + 1); CP_COMMIT(); CP_WAIT(1); }
        else              { CP_WAIT(0); }
        __syncthreads();

        const uint32_t base = sb + 2 * QMAT + (kt & 1) * FSTAGE;
        const uint32_t sKh = base, sKl = base + KVMAT;
        const uint32_t sVh = base + 2 * KVMAT, sVl = base + 3 * KVMAT;
        const int kvb = kt * BKV;

        // ---- S = Q K^T, pass-major (8 independent acc chains per pass) ----
        float s[8][4];
        #pragma unroll
        for (int i = 0; i < 8; i++)
            #pragma unroll
            for (int r = 0; r < 4; r++) s[i][r] = 0.0f;

        #pragma unroll
        for (int kc = 0; kc < 8; kc++) {
            uint32_t ah[4], al[4];
            ldsm4(ah, sQh + fsw(wrow + rl, 2 * kc + rh));
            ldsm4(al, sQl + fsw(wrow + rl, 2 * kc + rh));

            uint32_t bh[8][2], bl[8][2];
            #pragma unroll
            for (int nb = 0; nb < 4; nb++) {
                uint32_t rk[4], rkl[4];
                ldsm4(rk,  sKh + fsw(nb * 16 + rl, 2 * kc + rh));
                ldsm4(rkl, sKl + fsw(nb * 16 + rl, 2 * kc + rh));
                bh[2 * nb][0]     = rk[0];  bh[2 * nb][1]     = rk[2];
                bh[2 * nb + 1][0] = rk[1];  bh[2 * nb + 1][1] = rk[3];
                bl[2 * nb][0]     = rkl[0]; bl[2 * nb][1]     = rkl[2];
                bl[2 * nb + 1][0] = rkl[1]; bl[2 * nb + 1][1] = rkl[3];
            }
            // pass 1: hi*hi across all 8 accumulators
            #pragma unroll
            for (int nj = 0; nj < 8; nj++) mma16816(s[nj], ah, bh[nj]);
            // pass 2: hi*lo
            #pragma unroll
            for (int nj = 0; nj < 8; nj++) mma16816(s[nj], ah, bl[nj]);
            // pass 3: lo*hi
            #pragma unroll
            for (int nj = 0; nj < 8; nj++) mma16816(s[nj], al, bh[nj]);
        }

        // ---- scale + causal mask ----
        const bool needmask = (kt >= 2 * qt);
        #pragma unroll
        for (int nj = 0; nj < 8; nj++) {
            #pragma unroll
            for (int r = 0; r < 4; r++) {
                float v = s[nj][r] * scale;
                if (needmask) {
                    const int col = kvb + nj * 8 + 2 * ti + (r & 1);
                    const int row = (r & 2) ? row1 : row0;
                    if (col > row) v = -1e30f;
                }
                s[nj][r] = v;
            }
        }

        // ---- online softmax ----
        float mx0 = -1e30f, mx1 = -1e30f;
        #pragma unroll
        for (int nj = 0; nj < 8; nj++) {
            mx0 = fmaxf(mx0, fmaxf(s[nj][0], s[nj][1]));
            mx1 = fmaxf(mx1, fmaxf(s[nj][2], s[nj][3]));
        }
        mx0 = fmaxf(mx0, __shfl_xor_sync(0xffffffffu, mx0, 1));
        mx0 = fmaxf(mx0, __shfl_xor_sync(0xffffffffu, mx0, 2));
        mx1 = fmaxf(mx1, __shfl_xor_sync(0xffffffffu, mx1, 1));
        mx1 = fmaxf(mx1, __shfl_xor_sync(0xffffffffu, mx1, 2));
        const float mn0 = fmaxf(m0, mx0), mn1 = fmaxf(m1, mx1);
        const float cr0 = __expf(m0 - mn0), cr1 = __expf(m1 - mn1);
        m0 = mn0; m1 = mn1;

        float sum0 = 0.0f, sum1 = 0.0f;
        #pragma unroll
        for (int nj = 0; nj < 8; nj++) {
            s[nj][0] = __expf(s[nj][0] - mn0); sum0 += s[nj][0];
            s[nj][1] = __expf(s[nj][1] - mn0); sum0 += s[nj][1];
            s[nj][2] = __expf(s[nj][2] - mn1); sum1 += s[nj][2];
            s[nj][3] = __expf(s[nj][3] - mn1); sum1 += s[nj][3];
        }
        sum0 += __shfl_xor_sync(0xffffffffu, sum0, 1);
        sum0 += __shfl_xor_sync(0xffffffffu, sum0, 2);
        sum1 += __shfl_xor_sync(0xffffffffu, sum1, 1);
        sum1 += __shfl_xor_sync(0xffffffffu, sum1, 2);
        l0 = l0 * cr0 + sum0;
        l1 = l1 * cr1 + sum1;

        #pragma unroll
        for (int nj = 0; nj < 16; nj++) {
            o[nj][0] *= cr0; o[nj][1] *= cr0;
            o[nj][2] *= cr1; o[nj][3] *= cr1;
        }

        // ---- O += P V, pass-major over halves of 4 nb (8 indep chains/pass) ----
        #pragma unroll
        for (int kc = 0; kc < 4; kc++) {
            uint32_t pah[4], pal[4];
            {
                float la, lb;
                pah[0] = pack_hi_rz(s[2 * kc][0],     s[2 * kc][1],     la, lb); pal[0] = pack_rn(la, lb);
                pah[1] = pack_hi_rz(s[2 * kc][2],     s[2 * kc][3],     la, lb); pal[1] = pack_rn(la, lb);
                pah[2] = pack_hi_rz(s[2 * kc + 1][0], s[2 * kc + 1][1], la, lb); pal[2] = pack_rn(la, lb);
                pah[3] = pack_hi_rz(s[2 * kc + 1][2], s[2 * kc + 1][3], la, lb); pal[3] = pack_rn(la, lb);
            }
            #pragma unroll
            for (int half = 0; half < 2; half++) {
                uint32_t bv[8][2], cv[8][2];
                #pragma unroll
                for (int n4 = 0; n4 < 4; n4++) {
                    const int nb = half * 4 + n4;
                    uint32_t rv[4], rw[4];
                    const uint32_t so = fsw(kc * 16 + vro, 2 * nb + vco);
                    ldsm4t(rv, sVh + so);
                    ldsm4t(rw, sVl + so);
                    bv[2 * n4][0]     = rv[0]; bv[2 * n4][1]     = rv[1];
                    bv[2 * n4 + 1][0] = rv[2]; bv[2 * n4 + 1][1] = rv[3];
                    cv[2 * n4][0]     = rw[0]; cv[2 * n4][1]     = rw[1];
                    cv[2 * n4 + 1][0] = rw[2]; cv[2 * n4 + 1][1] = rw[3];
                }
                // pass 1: P_hi * V_hi across 8 o-accumulators
                #pragma unroll
                for (int j = 0; j < 8; j++) mma16816(o[8 * half + j], pah, bv[j]);
                // pass 2: P_hi * V_lo
                #pragma unroll
                for (int j = 0; j < 8; j++) mma16816(o[8 * half + j], pah, cv[j]);
                // pass 3: P_lo * V_hi
                #pragma unroll
                for (int j = 0; j < 8; j++) mma16816(o[8 * half + j], pal, bv[j]);
            }
        }
        __syncthreads();
    }

    // ---- epilogue: normalize, split hi/lo, store ----
    const float inv0 = 1.0f / l0, inv1 = 1.0f / l1;
    #pragma unroll
    for (int nj = 0; nj < 16; nj++) {
        const int col = h * HDIM + nj * 8 + 2 * ti;
        float v0 = o[nj][0] * inv0, v1 = o[nj][1] * inv0;
        float v2 = o[nj][2] * inv1, v3 = o[nj][3] * inv1;
        __nv_bfloat162 h0 = __floats2bfloat162_rn(v0, v1);
        __nv_bfloat162 h1 = __floats2bfloat162_rn(v2, v3);
        __nv_bfloat162 e0 = __floats2bfloat162_rn(v0 - __low2float(h0), v1 - __high2float(h0));
        __nv_bfloat162 e1 = __floats2bfloat162_rn(v2 - __low2float(h1), v3 - __high2float(h1));
        *(uint32_t*)&ath[(size_t)row0 * DIM + col] = *(uint32_t*)&h0;
        *(uint32_t*)&ath[(size_t)row1 * DIM + col] = *(uint32_t*)&h1;
        *(uint32_t*)&atl[(size_t)row0 * DIM + col] = *(uint32_t*)&e0;
        *(uint32_t*)&atl[(size_t)row1 * DIM + col] = *(uint32_t*)&e1;
    }
}

// ============================================================================
// launch
// ============================================================================
static inline void split_launch(const float* src, __nv_bfloat16* hi,
                                __nv_bfloat16* lo, int n)
{
    const int n4 = n / 4;
    split_kernel<<<(n4 + 255) / 256, 256>>>(src, hi, lo, n4);
}

extern "C" void kernel_launch(void* const* d_in, const int* in_sizes, int n_in,
                              void* d_out, int out_size)
{
    (void)in_sizes; (void)n_in; (void)out_size;
    const float* x  = (const float*)d_in[0];
    const float* wq = (const float*)d_in[1];
    const float* wk = (const float*)d_in[2];
    const float* wv = (const float*)d_in[3];
    const float* wo = (const float*)d_in[4];
    const float* fc = (const float*)d_in[5];
    const float* fs = (const float*)d_in[6];
    float* out = (float*)d_out;

    float *xq, *xk, *xv;
    __nv_bfloat16 *xh, *xl, *wqh, *wql, *wkh, *wkl, *wvh, *wvl, *woh, *wol;
    __nv_bfloat16 *ath, *atl, *qh, *ql, *kh, *kl, *vh, *vl;
    cudaGetSymbolAddress((void**)&xq, g_xq);
    cudaGetSymbolAddress((void**)&xk, g_xk);
    cudaGetSymbolAddress((void**)&xv, g_xv);
    cudaGetSymbolAddress((void**)&xh,  g_xh);  cudaGetSymbolAddress((void**)&xl,  g_xl);
    cudaGetSymbolAddress((void**)&wqh, g_wqh); cudaGetSymbolAddress((void**)&wql, g_wql);
    cudaGetSymbolAddress((void**)&wkh, g_wkh); cudaGetSymbolAddress((void**)&wkl, g_wkl);
    cudaGetSymbolAddress((void**)&wvh, g_wvh); cudaGetSymbolAddress((void**)&wvl, g_wvl);
    cudaGetSymbolAddress((void**)&woh, g_woh); cudaGetSymbolAddress((void**)&wol, g_wol);
    cudaGetSymbolAddress((void**)&ath, g_ath); cudaGetSymbolAddress((void**)&atl, g_atl);
    cudaGetSymbolAddress((void**)&qh,  g_qh);  cudaGetSymbolAddress((void**)&ql,  g_ql);
    cudaGetSymbolAddress((void**)&kh,  g_kh);  cudaGetSymbolAddress((void**)&kl,  g_kl);
    cudaGetSymbolAddress((void**)&vh,  g_vh);  cudaGetSymbolAddress((void**)&vl,  g_vl);

    cudaFuncSetAttribute(gemm_bf16x3_kernel,
                         cudaFuncAttributeMaxDynamicSharedMemorySize, GEMM_SMEM);
    cudaFuncSetAttribute(flash_tc_kernel,
                         cudaFuncAttributeMaxDynamicSharedMemorySize, FLASH_SMEM);

    // 0) split inputs to bf16 hi/lo
    split_launch(x,  xh,  xl,  SEQ * DIM);
    split_launch(wq, wqh, wql, DIM * DIM);
    split_launch(wk, wkh, wkl, KVDIM * DIM);
    split_launch(wv, wvh, wvl, KVDIM * DIM);
    split_launch(wo, woh, wol, DIM * DIM);

    // 1) Q projection (fp32 out)
    gemm_bf16x3_kernel<<<dim3(DIM / 128, SEQ / 128, 1), 256, GEMM_SMEM>>>(
        xh, xl, wqh, wql, xq, nullptr, nullptr, nullptr, SEQ, DIM, DIM);

    // 2) K and V projections fused
    gemm_bf16x3_kernel<<<dim3(KVDIM / 128, SEQ / 128, 2), 256, GEMM_SMEM>>>(
        xh, xl, wkh, wkl, xk, wvh, wvl, xv, SEQ, KVDIM, DIM);

    // 3) RoPE + split to bf16 hi/lo; split V
    {
        const int nq = SEQ * HEADS * (HDIM / 2);
        rope_split_kernel<<<(nq + 255) / 256, 256>>>(xq, fc, fs, qh, ql, HEADS);
        const int nk = SEQ * KVHEADS * (HDIM / 2);
        rope_split_kernel<<<(nk + 255) / 256, 256>>>(xk, fc, fs, kh, kl, KVHEADS);
        split_launch(xv, vh, vl, SEQ * KVDIM);
    }

    // 4) tensor-core flash attention -> attn hi/lo
    flash_tc_kernel<<<dim3(SEQ / BQ, HEADS), 256, FLASH_SMEM>>>(
        qh, ql, kh, kl, vh, vl, ath, atl);

    // 5) O projection
    gemm_bf16x3_kernel<<<dim3(DIM / 128, SEQ / 128, 1), 256, GEMM_SMEM>>>(
        ath, atl, woh, wol, out, nullptr, nullptr, nullptr, SEQ, DIM, DIM);
}